// round 1
// baseline (speedup 1.0000x reference)
#include <cuda_runtime.h>
#include <cstdint>

// ConcatenateMeanMax: out[b] = concat(bond_ft[b], mean(atom_ft[src0], atom_ft[src1]),
//                                     max(atom_ft[src0], atom_ft[src1]))
// with src_k = edge_src[DEG*b + k], DEG = 2 (edge_dst is repeat(arange(n_bonds), 2)).
//
// Layout: D = 128 floats = 32 float4. One warp per bond; each lane owns one float4
// column slice. All loads/stores are 512B-contiguous per warp.

constexpr int D  = 128;
constexpr int DV = D / 4;  // 32 float4 per row

__global__ __launch_bounds__(256)
void concat_mean_max_kernel(const float4* __restrict__ atom_ft,
                            const float4* __restrict__ bond_ft,
                            const int2*  __restrict__ edge_src2,
                            float4* __restrict__ out,
                            int n_bonds)
{
    const int gwarp = (blockIdx.x * blockDim.x + threadIdx.x) >> 5;
    const int lane  = threadIdx.x & 31;
    if (gwarp >= n_bonds) return;

    // Both source atom indices for this bond (same address across lanes -> L1 broadcast).
    const int2 s = __ldg(&edge_src2[gwarp]);

    const float4 a0 = __ldg(&atom_ft[(long long)s.x * DV + lane]);
    const float4 a1 = __ldg(&atom_ft[(long long)s.y * DV + lane]);
    const float4 bf = __ldg(&bond_ft[(long long)gwarp * DV + lane]);

    float4 mean_v, max_v;
    mean_v.x = (a0.x + a1.x) * 0.5f;  max_v.x = fmaxf(a0.x, a1.x);
    mean_v.y = (a0.y + a1.y) * 0.5f;  max_v.y = fmaxf(a0.y, a1.y);
    mean_v.z = (a0.z + a1.z) * 0.5f;  max_v.z = fmaxf(a0.z, a1.z);
    mean_v.w = (a0.w + a1.w) * 0.5f;  max_v.w = fmaxf(a0.w, a1.w);

    float4* orow = out + (long long)gwarp * (3 * DV);
    orow[lane]          = bf;      // [0:128)   bond features
    orow[DV + lane]     = mean_v;  // [128:256) segment mean
    orow[2 * DV + lane] = max_v;   // [256:384) segment max
}

extern "C" void kernel_launch(void* const* d_in, const int* in_sizes, int n_in,
                              void* d_out, int out_size)
{
    const float4* atom_ft  = (const float4*)d_in[0];   // [N_ATOMS, 128] f32
    const float4* bond_ft  = (const float4*)d_in[1];   // [N_BONDS, 128] f32
    const int2*   edge_src = (const int2*)d_in[2];     // [N_BONDS*2] i32, viewed as int2 per bond
    // d_in[3] = edge_dst (structurally repeat(arange, 2)) -- not needed.

    const int n_bonds = in_sizes[1] / D;

    const int threads = 256;                 // 8 warps/block
    const int warps_per_block = threads / 32;
    const int blocks = (n_bonds + warps_per_block - 1) / warps_per_block;

    concat_mean_max_kernel<<<blocks, threads>>>(
        atom_ft, bond_ft, edge_src, (float4*)d_out, n_bonds);
}

// round 2
// speedup vs baseline: 1.0531x; 1.0531x over previous
#include <cuda_runtime.h>
#include <cstdint>

// ConcatenateMeanMax: out[b] = concat(bond_ft[b], mean(atom_ft[src0], atom_ft[src1]),
//                                     max(atom_ft[src0], atom_ft[src1]))
// DEG = 2 fixed (edge_dst is repeat(arange(n_bonds), 2)).
//
// One warp per bond; lane owns one float4 (32 x 16B = 512B = full D=128 row).
//
// Cache policy: atom_ft is the ONLY stream with reuse (102.4 MB table, ~4x avg
// reuse, fits in 126 MB L2). bond_ft (read-once) uses evict-first loads and the
// output (write-once) uses streaming stores so neither evicts atom rows from L2.

constexpr int D  = 128;
constexpr int DV = D / 4;  // 32 float4 per row

__global__ __launch_bounds__(256)
void concat_mean_max_kernel(const float4* __restrict__ atom_ft,
                            const float4* __restrict__ bond_ft,
                            const int2*  __restrict__ edge_src2,
                            float4* __restrict__ out,
                            int n_bonds)
{
    const int gwarp = (blockIdx.x * blockDim.x + threadIdx.x) >> 5;
    const int lane  = threadIdx.x & 31;
    if (gwarp >= n_bonds) return;

    const int2 s = __ldg(&edge_src2[gwarp]);

    // read-once bond row: streaming (evict-first) load
    const float4 bf = __ldcs(&bond_ft[(long long)gwarp * DV + lane]);

    // reused atom rows: default caching (stay resident in L2)
    const float4 a0 = __ldg(&atom_ft[(long long)s.x * DV + lane]);
    const float4 a1 = __ldg(&atom_ft[(long long)s.y * DV + lane]);

    float4 mean_v, max_v;
    mean_v.x = (a0.x + a1.x) * 0.5f;  max_v.x = fmaxf(a0.x, a1.x);
    mean_v.y = (a0.y + a1.y) * 0.5f;  max_v.y = fmaxf(a0.y, a1.y);
    mean_v.z = (a0.z + a1.z) * 0.5f;  max_v.z = fmaxf(a0.z, a1.z);
    mean_v.w = (a0.w + a1.w) * 0.5f;  max_v.w = fmaxf(a0.w, a1.w);

    float4* orow = out + (long long)gwarp * (3 * DV);
    // write-once output: streaming stores (don't allocate in L2 at normal priority)
    __stcs(orow + lane,          bf);
    __stcs(orow + DV + lane,     mean_v);
    __stcs(orow + 2 * DV + lane, max_v);
}

extern "C" void kernel_launch(void* const* d_in, const int* in_sizes, int n_in,
                              void* d_out, int out_size)
{
    const float4* atom_ft  = (const float4*)d_in[0];   // [N_ATOMS, 128] f32
    const float4* bond_ft  = (const float4*)d_in[1];   // [N_BONDS, 128] f32
    const int2*   edge_src = (const int2*)d_in[2];     // [N_BONDS*2] i32 -> int2 per bond
    // d_in[3] = edge_dst (structurally repeat(arange, 2)) -- not needed.

    const int n_bonds = in_sizes[1] / D;

    const int threads = 256;                 // 8 warps/block
    const int warps_per_block = threads / 32;
    const int blocks = (n_bonds + warps_per_block - 1) / warps_per_block;

    concat_mean_max_kernel<<<blocks, threads>>>(
        atom_ft, bond_ft, edge_src, (float4*)d_out, n_bonds);
}